// round 14
// baseline (speedup 1.0000x reference)
#include <cuda_runtime.h>
#include <cuda_fp16.h>
#include <stdint.h>
#include <math.h>

// ---------------- problem dims ----------------
#define BATCH 256
#define TSTEPS 250
#define INDIM 700
#define HDIM 256
#define ODIM 20
#define KBR 4
#define BT (BATCH * TSTEPS)   // 64000
#define INPAD 704
#define HK 1024               // H*K
#define NR 32                 // padded readout rows (20 -> 32)
#define HBATCH (BATCH / 2)    // 128 batches per half
#define HROWS (BT / 2)        // 32000 rows per half

// ---------------- scratch ----------------
__device__ __align__(16) __half g_Xh[(size_t)BT * INPAD];    // 90 MB
__device__ __align__(16) __half g_W1h[(size_t)HK * INPAD];
__device__ __align__(16) __half g_W2h[(size_t)HK * HDIM];
__device__ __align__(16) __half g_Wrh[(size_t)NR * HDIM];
__device__ __align__(16) __half g_C[(size_t)BT * HK];        // 131 MB fp16
__device__ __align__(16) __half g_S1[(size_t)BT * HDIM];
__device__ __align__(16) __half g_S2[(size_t)BT * HDIM];

// ---------------- prep kernels ----------------
__global__ void prep_x_kernel(const float* __restrict__ x, int rbase) {
    size_t i = (size_t)blockIdx.x * blockDim.x + threadIdx.x;
    int r = rbase + (int)(i / (INPAD / 4));
    int c4 = (int)(i % (INPAD / 4)) * 4;
    __half2 h01 = __floats2half2_rn(0.f, 0.f), h23 = h01;
    if (c4 < INDIM) {
        float4 v = *(const float4*)(x + (size_t)r * INDIM + c4);
        h01 = __floats2half2_rn(v.x > 0.5f ? 1.f : 0.f, v.y > 0.5f ? 1.f : 0.f);
        h23 = __floats2half2_rn(v.z > 0.5f ? 1.f : 0.f, v.w > 0.5f ? 1.f : 0.f);
    }
    __half2* p = (__half2*)(g_Xh + (size_t)r * INPAD + c4);
    p[0] = h01;
    p[1] = h23;
}

#define NW1B ((HK * INPAD) / 256)              // 2816
#define NW2B ((HK * HDIM) / 256)               // 1024
#define NWRB ((NR * HDIM) / 256)               // 32

__device__ __forceinline__ void prep_w_elem(const float* __restrict__ W, __half* dst,
                                            int i, int Nin, int Kin, int Kpad) {
    int n = i / Kpad;
    int c = i % Kpad;
    float v = (n < Nin && c < Kin) ? W[(size_t)n * Kin + c] : 0.f;
    dst[i] = __float2half_rn(v);
}

__global__ void prep_w_all(const float* __restrict__ W1, const float* __restrict__ W2,
                           const float* __restrict__ Wr) {
    const int blk = blockIdx.x;
    const int tid = threadIdx.x;
    if (blk < NW1B) prep_w_elem(W1, g_W1h, blk * 256 + tid, HK, INDIM, INPAD);
    else if (blk < NW1B + NW2B) prep_w_elem(W2, g_W2h, (blk - NW1B) * 256 + tid, HK, HDIM, HDIM);
    else prep_w_elem(Wr, g_Wrh, (blk - NW1B - NW2B) * 256 + tid, ODIM, HDIM, HDIM);
}

// ---------------- asm helpers ----------------
__device__ __forceinline__ uint32_t smem_u32(const void* p) {
    uint32_t a;
    asm("{ .reg .u64 t; cvta.to.shared.u64 t, %1; cvt.u32.u64 %0, t; }" : "=r"(a) : "l"(p));
    return a;
}
__device__ __forceinline__ void cp16s(uint32_t d, const void* s) {
    asm volatile("cp.async.cg.shared.global [%0], [%1], 16;\n" :: "r"(d), "l"(s));
}
#define CP_COMMIT() asm volatile("cp.async.commit_group;\n")
#define CP_WAIT(n)  asm volatile("cp.async.wait_group %0;\n" :: "n"(n))

__device__ __forceinline__ void ldsm4(uint32_t (&r)[4], uint32_t addr) {
    asm volatile("ldmatrix.sync.aligned.m8n8.x4.shared.b16 {%0,%1,%2,%3}, [%4];"
                 : "=r"(r[0]), "=r"(r[1]), "=r"(r[2]), "=r"(r[3]) : "r"(addr));
}
__device__ __forceinline__ void mma16816(float (&d)[4], const uint32_t (&a)[4],
                                         const uint32_t b0, const uint32_t b1) {
    asm volatile(
        "mma.sync.aligned.m16n8k16.row.col.f32.f16.f16.f32 "
        "{%0,%1,%2,%3}, {%4,%5,%6,%7}, {%8,%9}, {%0,%1,%2,%3};\n"
        : "+f"(d[0]), "+f"(d[1]), "+f"(d[2]), "+f"(d[3])
        : "r"(a[0]), "r"(a[1]), "r"(a[2]), "r"(a[3]), "r"(b0), "r"(b1));
}

// ---------------- fp16 GEMM (R11 body + y-tile offset) ----------------
#define ROWB 144
#define NSTG 3

template <int KEXT, int NTILE>
__device__ __forceinline__ void gemm_body(const __half* __restrict__ A, int lda,
                                          const __half* __restrict__ B, int ldb,
                                          __half* __restrict__ C, int ldc, int yoff) {
    constexpr int NSLAB = KEXT / 64;
    constexpr int ASTB = 128 * ROWB;
    constexpr int BSTB = NTILE * ROWB;
    constexpr int NT = NTILE / 16;

    extern __shared__ __align__(16) char smem[];
    const uint32_t sbA = smem_u32(smem);
    const uint32_t sbB = sbA + NSTG * ASTB;

    const int tid = threadIdx.x;
    const int lane = tid & 31, warp = tid >> 5;
    const int wm = warp & 3;
    const int wn = warp >> 2;
    const int m0 = (blockIdx.y + yoff) * 128;
    const int n0 = blockIdx.x * NTILE;

    float acc[2][NT][4];
#pragma unroll
    for (int i = 0; i < 2; ++i)
#pragma unroll
        for (int j = 0; j < NT; ++j)
#pragma unroll
            for (int q = 0; q < 4; ++q) acc[i][j][q] = 0.f;

    const int frow = tid >> 3;
    const int fch = (tid & 7) * 16;

    auto fill = [&](int s) {
        const int st = s % NSTG;
        const int kb = s * 64;
        const __half* Ab = A + (size_t)(m0 + frow) * lda + kb + (fch >> 1);
        const __half* Bb = B + (size_t)(n0 + frow) * ldb + kb + (fch >> 1);
        uint32_t dA = sbA + st * ASTB + frow * ROWB + fch;
        uint32_t dB = sbB + st * BSTB + frow * ROWB + fch;
#pragma unroll
        for (int i = 0; i < 4; ++i)
            cp16s(dA + i * 32 * ROWB, Ab + (size_t)i * 32 * lda);
#pragma unroll
        for (int i = 0; i < NTILE / 32; ++i)
            cp16s(dB + i * 32 * ROWB, Bb + (size_t)i * 32 * ldb);
        CP_COMMIT();
    };

    fill(0); fill(1);

    const uint32_t aOff = (uint32_t)(wm * 32 + (lane & 15)) * ROWB + ((lane >> 4) << 4);
    const uint32_t bOff = (uint32_t)(wn * (NTILE / 2) + (lane & 7) + ((lane >> 4) & 1) * 8) * ROWB
                        + (((lane >> 3) & 1) << 4);

    for (int s = 0; s < NSLAB; ++s) {
        if (s + 1 < NSLAB) CP_WAIT(1);
        else CP_WAIT(0);
        __syncthreads();
        if (s + 2 < NSLAB) fill(s + 2);

        const uint32_t sA = sbA + (s % NSTG) * ASTB;
        const uint32_t sB = sbB + (s % NSTG) * BSTB;
#pragma unroll
        for (int kk = 0; kk < 4; ++kk) {
            uint32_t a[2][4];
#pragma unroll
            for (int mt = 0; mt < 2; ++mt)
                ldsm4(a[mt], sA + aOff + (uint32_t)mt * 16 * ROWB + kk * 32);
            uint32_t b[NT / 2][4];
#pragma unroll
            for (int np = 0; np < NT / 2; ++np)
                ldsm4(b[np], sB + bOff + (uint32_t)np * 16 * ROWB + kk * 32);
#pragma unroll
            for (int mt = 0; mt < 2; ++mt)
#pragma unroll
                for (int nt = 0; nt < NT; ++nt)
                    mma16816(acc[mt][nt], a[mt], b[nt >> 1][(nt & 1) * 2],
                             b[nt >> 1][(nt & 1) * 2 + 1]);
        }
    }

#pragma unroll
    for (int mt = 0; mt < 2; ++mt) {
        const int row = m0 + wm * 32 + mt * 16 + (lane >> 2);
        __half* Cr0 = C + (size_t)row * ldc + n0 + wn * (NTILE / 2) + (lane & 3) * 2;
        __half* Cr1 = Cr0 + (size_t)8 * ldc;
#pragma unroll
        for (int nt = 0; nt < NT; ++nt) {
            *(__half2*)(Cr0 + nt * 8) = __floats2half2_rn(acc[mt][nt][0], acc[mt][nt][1]);
            *(__half2*)(Cr1 + nt * 8) = __floats2half2_rn(acc[mt][nt][2], acc[mt][nt][3]);
        }
    }
}

__global__ __launch_bounds__(256, 2) void gemm1_k(int yoff) {
    gemm_body<INPAD, 128>(g_Xh, INPAD, g_W1h, INPAD, g_C, HK, yoff);
}
__global__ __launch_bounds__(256, 2) void gemm2_k(int yoff) {
    gemm_body<HDIM, 128>(g_S1, HDIM, g_W2h, HDIM, g_C, HK, yoff);
}
__global__ __launch_bounds__(256, 2) void gemm3_k(int yoff) {
    gemm_body<HDIM, 32>(g_S2, HDIM, g_Wrh, HDIM, g_C, NR, yoff);
}

// ---------------- time scans (half-batch, boff) ----------------
__global__ void scan_layer_kernel(const float* __restrict__ bias,
                                  const float* __restrict__ tau_n,
                                  const float* __restrict__ tau_m,
                                  int which, int boff) {
    const int b = boff + (blockIdx.x >> 1);
    const int h = ((blockIdx.x & 1) << 7) + threadIdx.x;
    __half* S = which ? g_S2 : g_S1;

    float be[KBR], ob[KBR], bi[KBR];
#pragma unroll
    for (int k = 0; k < KBR; ++k) {
        float s = 1.f / (1.f + expf(-tau_n[h * KBR + k]));
        be[k] = s;
        ob[k] = 1.f - s;
        bi[k] = bias[h * KBR + k];
    }
    float al = 1.f / (1.f + expf(-tau_m[h]));
    float oa = 1.f - al;

    float d0 = 0.f, d1 = 0.f, d2 = 0.f, d3 = 0.f, m = 0.f, sp = 0.f;
    const uint2* Cf = (const uint2*)g_C;
    size_t base = (size_t)b * TSTEPS * (HK / 4) + h;

#pragma unroll 10
    for (int t = 0; t < TSTEPS; ++t) {
        uint2 cv = Cf[base + (size_t)t * (HK / 4)];
        float2 c01 = __half22float2(*(__half2*)&cv.x);
        float2 c23 = __half22float2(*(__half2*)&cv.y);
        d0 = be[0] * d0 + ob[0] * (c01.x + bi[0]);
        d1 = be[1] * d1 + ob[1] * (c01.y + bi[1]);
        d2 = be[2] * d2 + ob[2] * (c23.x + bi[2]);
        d3 = be[3] * d3 + ob[3] * (c23.y + bi[3]);
        m = al * m + oa * (d0 + d1 + d2 + d3) - sp;
        sp = (m > 1.0f) ? 1.0f : 0.0f;
        S[((size_t)b * TSTEPS + t) * HDIM + h] = __float2half_rn(sp);
    }
}

__global__ void scan_readout_kernel(const float* __restrict__ br,
                                    const float* __restrict__ tau_mr,
                                    const void* __restrict__ warm,
                                    float* __restrict__ out, int boff) {
    const int o = threadIdx.x;
    const int b = boff + blockIdx.x;
    if (o >= ODIM) return;
    int w = *(const int*)warm;
    if (w < 0 || w > TSTEPS) w = (int)(*(const float*)warm);
    float al = 1.f / (1.f + expf(-tau_mr[o]));
    float oa = 1.f - al;
    float bo = br[o];
    float mr = 0.f, acc = 0.f;
    size_t base = (size_t)b * TSTEPS * NR + o;
#pragma unroll 10
    for (int t = 0; t < TSTEPS; ++t) {
        float v = __half2float(g_C[base + (size_t)t * NR]);
        mr = al * mr + oa * (v + bo);
        if (t >= w) acc += mr;
    }
    out[b * ODIM + o] = acc / (float)(TSTEPS - w);
}

// ---------------- launch: 2-stream STAGGERED pipeline ----------------
static cudaStream_t g_s1 = nullptr;
static cudaEvent_t g_ev0, g_evW, g_evA, g_ev1;

extern "C" void kernel_launch(void* const* d_in, const int* in_sizes, int n_in,
                              void* d_out, int out_size) {
    const float* x      = (const float*)d_in[0];
    const float* W1     = (const float*)d_in[1];
    const float* b1     = (const float*)d_in[2];
    const float* tau_n1 = (const float*)d_in[3];
    const float* tau_m1 = (const float*)d_in[4];
    const float* W2     = (const float*)d_in[5];
    const float* b2     = (const float*)d_in[6];
    const float* tau_n2 = (const float*)d_in[7];
    const float* tau_m2 = (const float*)d_in[8];
    const float* Wr     = (const float*)d_in[9];
    const float* br     = (const float*)d_in[10];
    const float* tau_mr = (const float*)d_in[11];
    const void*  warm   = d_in[12];
    float* out = (float*)d_out;

    if (!g_s1) {   // host-side resources, created once
        cudaStreamCreateWithFlags(&g_s1, cudaStreamNonBlocking);
        cudaEventCreateWithFlags(&g_ev0, cudaEventDisableTiming);
        cudaEventCreateWithFlags(&g_evW, cudaEventDisableTiming);
        cudaEventCreateWithFlags(&g_evA, cudaEventDisableTiming);
        cudaEventCreateWithFlags(&g_ev1, cudaEventDisableTiming);
    }

    const int smem12 = NSTG * (128 + 128) * ROWB;  // 110592 per CTA
    const int smem3  = NSTG * (128 + 32) * ROWB;   // 69120
    cudaFuncSetAttribute(gemm1_k, cudaFuncAttributeMaxDynamicSharedMemorySize, smem12);
    cudaFuncSetAttribute(gemm2_k, cudaFuncAttributeMaxDynamicSharedMemorySize, smem12);
    cudaFuncSetAttribute(gemm3_k, cudaFuncAttributeMaxDynamicSharedMemorySize, smem3);

    const int xblk = (HROWS * (INPAD / 4)) / 256;   // 22000 per half

    // fork side stream
    cudaEventRecord(g_ev0, 0);
    cudaStreamWaitEvent(g_s1, g_ev0, 0);

    // ---- default stream (half 0) ----
    prep_w_all<<<NW1B + NW2B + NWRB, 256>>>(W1, W2, Wr);                          // #0
    cudaEventRecord(g_evW, 0);
    prep_x_kernel<<<xblk, 256>>>(x, 0);                                           // #1
    gemm1_k<<<dim3(8, 250), 256, smem12>>>(0);                                    // #2
    cudaEventRecord(g_evA, 0);   // stagger anchor: h1 GEMMs start after this
    scan_layer_kernel<<<2 * HBATCH, 128>>>(b1, tau_n1, tau_m1, 0, 0);             // #3 <- profiled
    gemm2_k<<<dim3(8, 250), 256, smem12>>>(0);
    scan_layer_kernel<<<2 * HBATCH, 128>>>(b2, tau_n2, tau_m2, 1, 0);
    gemm3_k<<<dim3(1, 250), 256, smem3>>>(0);
    scan_readout_kernel<<<HBATCH, 32>>>(br, tau_mr, warm, out, 0);

    // ---- side stream (half 1), staggered by one GEMM phase ----
    prep_x_kernel<<<xblk, 256, 0, g_s1>>>(x, HROWS);   // runs early (indep of weights)
    cudaStreamWaitEvent(g_s1, g_evW, 0);
    cudaStreamWaitEvent(g_s1, g_evA, 0);               // phase shift: after gemm1(h0)
    gemm1_k<<<dim3(8, 250), 256, smem12, g_s1>>>(250);
    scan_layer_kernel<<<2 * HBATCH, 128, 0, g_s1>>>(b1, tau_n1, tau_m1, 0, HBATCH);
    gemm2_k<<<dim3(8, 250), 256, smem12, g_s1>>>(250);
    scan_layer_kernel<<<2 * HBATCH, 128, 0, g_s1>>>(b2, tau_n2, tau_m2, 1, HBATCH);
    gemm3_k<<<dim3(1, 250), 256, smem3, g_s1>>>(250);
    scan_readout_kernel<<<HBATCH, 32, 0, g_s1>>>(br, tau_mr, warm, out, HBATCH);
    cudaEventRecord(g_ev1, g_s1);

    // join
    cudaStreamWaitEvent(0, g_ev1, 0);
}

// round 15
// speedup vs baseline: 1.4666x; 1.4666x over previous
#include <cuda_runtime.h>
#include <cuda_fp16.h>
#include <stdint.h>
#include <math.h>

// ---------------- problem dims ----------------
#define BATCH 256
#define TSTEPS 250
#define INDIM 700
#define HDIM 256
#define ODIM 20
#define KBR 4
#define BT (BATCH * TSTEPS)   // 64000
#define INPAD 704
#define HK 1024               // H*K
#define NR 32                 // padded readout rows (20 -> 32)
#define HBATCH (BATCH / 2)    // 128 batches per half
#define HROWS (BT / 2)        // 32000 rows per half

// ---------------- scratch ----------------
__device__ __align__(16) __half g_Xh[(size_t)BT * INPAD];    // 90 MB
__device__ __align__(16) __half g_W1h[(size_t)HK * INPAD];
__device__ __align__(16) __half g_W2h[(size_t)HK * HDIM];
__device__ __align__(16) __half g_Wrh[(size_t)NR * HDIM];
__device__ __align__(16) __half g_C[(size_t)BT * HK];        // 131 MB fp16
__device__ __align__(16) __half g_S1[(size_t)BT * HDIM];
__device__ __align__(16) __half g_S2[(size_t)BT * HDIM];

// ---------------- prep kernels ----------------
__global__ void prep_x_kernel(const float* __restrict__ x, int rbase) {
    size_t i = (size_t)blockIdx.x * blockDim.x + threadIdx.x;
    int r = rbase + (int)(i / (INPAD / 4));
    int c4 = (int)(i % (INPAD / 4)) * 4;
    __half2 h01 = __floats2half2_rn(0.f, 0.f), h23 = h01;
    if (c4 < INDIM) {
        float4 v = *(const float4*)(x + (size_t)r * INDIM + c4);
        h01 = __floats2half2_rn(v.x > 0.5f ? 1.f : 0.f, v.y > 0.5f ? 1.f : 0.f);
        h23 = __floats2half2_rn(v.z > 0.5f ? 1.f : 0.f, v.w > 0.5f ? 1.f : 0.f);
    }
    __half2* p = (__half2*)(g_Xh + (size_t)r * INPAD + c4);
    p[0] = h01;
    p[1] = h23;
}

#define NW1B ((HK * INPAD) / 256)              // 2816
#define NW2B ((HK * HDIM) / 256)               // 1024
#define NWRB ((NR * HDIM) / 256)               // 32

__device__ __forceinline__ void prep_w_elem(const float* __restrict__ W, __half* dst,
                                            int i, int Nin, int Kin, int Kpad) {
    int n = i / Kpad;
    int c = i % Kpad;
    float v = (n < Nin && c < Kin) ? W[(size_t)n * Kin + c] : 0.f;
    dst[i] = __float2half_rn(v);
}

__global__ void prep_w_all(const float* __restrict__ W1, const float* __restrict__ W2,
                           const float* __restrict__ Wr) {
    const int blk = blockIdx.x;
    const int tid = threadIdx.x;
    if (blk < NW1B) prep_w_elem(W1, g_W1h, blk * 256 + tid, HK, INDIM, INPAD);
    else if (blk < NW1B + NW2B) prep_w_elem(W2, g_W2h, (blk - NW1B) * 256 + tid, HK, HDIM, HDIM);
    else prep_w_elem(Wr, g_Wrh, (blk - NW1B - NW2B) * 256 + tid, ODIM, HDIM, HDIM);
}

// ---------------- asm helpers ----------------
__device__ __forceinline__ uint32_t smem_u32(const void* p) {
    uint32_t a;
    asm("{ .reg .u64 t; cvta.to.shared.u64 t, %1; cvt.u32.u64 %0, t; }" : "=r"(a) : "l"(p));
    return a;
}
__device__ __forceinline__ void cp16s(uint32_t d, const void* s) {
    asm volatile("cp.async.cg.shared.global [%0], [%1], 16;\n" :: "r"(d), "l"(s));
}
#define CP_COMMIT() asm volatile("cp.async.commit_group;\n")
#define CP_WAIT(n)  asm volatile("cp.async.wait_group %0;\n" :: "n"(n))

__device__ __forceinline__ void ldsm4(uint32_t (&r)[4], uint32_t addr) {
    asm volatile("ldmatrix.sync.aligned.m8n8.x4.shared.b16 {%0,%1,%2,%3}, [%4];"
                 : "=r"(r[0]), "=r"(r[1]), "=r"(r[2]), "=r"(r[3]) : "r"(addr));
}
__device__ __forceinline__ void mma16816(float (&d)[4], const uint32_t (&a)[4],
                                         const uint32_t b0, const uint32_t b1) {
    asm volatile(
        "mma.sync.aligned.m16n8k16.row.col.f32.f16.f16.f32 "
        "{%0,%1,%2,%3}, {%4,%5,%6,%7}, {%8,%9}, {%0,%1,%2,%3};\n"
        : "+f"(d[0]), "+f"(d[1]), "+f"(d[2]), "+f"(d[3])
        : "r"(a[0]), "r"(a[1]), "r"(a[2]), "r"(a[3]), "r"(b0), "r"(b1));
}

// ---------------- fp16 GEMM (R11 body + y-tile offset) ----------------
#define ROWB 144
#define NSTG 3

template <int KEXT, int NTILE>
__device__ __forceinline__ void gemm_body(const __half* __restrict__ A, int lda,
                                          const __half* __restrict__ B, int ldb,
                                          __half* __restrict__ C, int ldc, int yoff) {
    constexpr int NSLAB = KEXT / 64;
    constexpr int ASTB = 128 * ROWB;
    constexpr int BSTB = NTILE * ROWB;
    constexpr int NT = NTILE / 16;

    extern __shared__ __align__(16) char smem[];
    const uint32_t sbA = smem_u32(smem);
    const uint32_t sbB = sbA + NSTG * ASTB;

    const int tid = threadIdx.x;
    const int lane = tid & 31, warp = tid >> 5;
    const int wm = warp & 3;
    const int wn = warp >> 2;
    const int m0 = (blockIdx.y + yoff) * 128;
    const int n0 = blockIdx.x * NTILE;

    float acc[2][NT][4];
#pragma unroll
    for (int i = 0; i < 2; ++i)
#pragma unroll
        for (int j = 0; j < NT; ++j)
#pragma unroll
            for (int q = 0; q < 4; ++q) acc[i][j][q] = 0.f;

    const int frow = tid >> 3;
    const int fch = (tid & 7) * 16;

    auto fill = [&](int s) {
        const int st = s % NSTG;
        const int kb = s * 64;
        const __half* Ab = A + (size_t)(m0 + frow) * lda + kb + (fch >> 1);
        const __half* Bb = B + (size_t)(n0 + frow) * ldb + kb + (fch >> 1);
        uint32_t dA = sbA + st * ASTB + frow * ROWB + fch;
        uint32_t dB = sbB + st * BSTB + frow * ROWB + fch;
#pragma unroll
        for (int i = 0; i < 4; ++i)
            cp16s(dA + i * 32 * ROWB, Ab + (size_t)i * 32 * lda);
#pragma unroll
        for (int i = 0; i < NTILE / 32; ++i)
            cp16s(dB + i * 32 * ROWB, Bb + (size_t)i * 32 * ldb);
        CP_COMMIT();
    };

    fill(0); fill(1);

    const uint32_t aOff = (uint32_t)(wm * 32 + (lane & 15)) * ROWB + ((lane >> 4) << 4);
    const uint32_t bOff = (uint32_t)(wn * (NTILE / 2) + (lane & 7) + ((lane >> 4) & 1) * 8) * ROWB
                        + (((lane >> 3) & 1) << 4);

    for (int s = 0; s < NSLAB; ++s) {
        if (s + 1 < NSLAB) CP_WAIT(1);
        else CP_WAIT(0);
        __syncthreads();
        if (s + 2 < NSLAB) fill(s + 2);

        const uint32_t sA = sbA + (s % NSTG) * ASTB;
        const uint32_t sB = sbB + (s % NSTG) * BSTB;
#pragma unroll
        for (int kk = 0; kk < 4; ++kk) {
            uint32_t a[2][4];
#pragma unroll
            for (int mt = 0; mt < 2; ++mt)
                ldsm4(a[mt], sA + aOff + (uint32_t)mt * 16 * ROWB + kk * 32);
            uint32_t b[NT / 2][4];
#pragma unroll
            for (int np = 0; np < NT / 2; ++np)
                ldsm4(b[np], sB + bOff + (uint32_t)np * 16 * ROWB + kk * 32);
#pragma unroll
            for (int mt = 0; mt < 2; ++mt)
#pragma unroll
                for (int nt = 0; nt < NT; ++nt)
                    mma16816(acc[mt][nt], a[mt], b[nt >> 1][(nt & 1) * 2],
                             b[nt >> 1][(nt & 1) * 2 + 1]);
        }
    }

#pragma unroll
    for (int mt = 0; mt < 2; ++mt) {
        const int row = m0 + wm * 32 + mt * 16 + (lane >> 2);
        __half* Cr0 = C + (size_t)row * ldc + n0 + wn * (NTILE / 2) + (lane & 3) * 2;
        __half* Cr1 = Cr0 + (size_t)8 * ldc;
#pragma unroll
        for (int nt = 0; nt < NT; ++nt) {
            *(__half2*)(Cr0 + nt * 8) = __floats2half2_rn(acc[mt][nt][0], acc[mt][nt][1]);
            *(__half2*)(Cr1 + nt * 8) = __floats2half2_rn(acc[mt][nt][2], acc[mt][nt][3]);
        }
    }
}

__global__ __launch_bounds__(256, 2) void gemm1_k(int yoff) {
    gemm_body<INPAD, 128>(g_Xh, INPAD, g_W1h, INPAD, g_C, HK, yoff);
}
__global__ __launch_bounds__(256, 2) void gemm2_k(int yoff) {
    gemm_body<HDIM, 128>(g_S1, HDIM, g_W2h, HDIM, g_C, HK, yoff);
}
__global__ __launch_bounds__(256, 2) void gemm3_k(int yoff) {
    gemm_body<HDIM, 32>(g_S2, HDIM, g_Wrh, HDIM, g_C, NR, yoff);
}

// ---------------- time scans: explicit double-buffered prefetch ----------------
#define SCH 10   // chunk size (250 = 25 * 10)

__global__ void scan_layer_kernel(const float* __restrict__ bias,
                                  const float* __restrict__ tau_n,
                                  const float* __restrict__ tau_m,
                                  int which, int boff) {
    const int b = boff + (blockIdx.x >> 1);
    const int h = ((blockIdx.x & 1) << 7) + threadIdx.x;
    __half* S = which ? g_S2 : g_S1;

    float be[KBR], ob[KBR], bi[KBR];
#pragma unroll
    for (int k = 0; k < KBR; ++k) {
        float s = 1.f / (1.f + expf(-tau_n[h * KBR + k]));
        be[k] = s;
        ob[k] = 1.f - s;
        bi[k] = bias[h * KBR + k];
    }
    float al = 1.f / (1.f + expf(-tau_m[h]));
    float oa = 1.f - al;

    const uint2* Cf = (const uint2*)g_C;
    const size_t base = (size_t)b * TSTEPS * (HK / 4) + h;
    __half* Sp = S + (size_t)b * TSTEPS * HDIM + h;

    uint2 buf[2][SCH];
#pragma unroll
    for (int j = 0; j < SCH; ++j)           // preload chunk 0 (10 independent loads)
        buf[0][j] = Cf[base + (size_t)j * (HK / 4)];

    float d0 = 0.f, d1 = 0.f, d2 = 0.f, d3 = 0.f, m = 0.f, sp = 0.f;

    for (int c = 0; c < TSTEPS / SCH; ++c) {
        const int cur = c & 1;
        if (c + 1 < TSTEPS / SCH) {         // prefetch next chunk while computing
#pragma unroll
            for (int j = 0; j < SCH; ++j)
                buf[cur ^ 1][j] = Cf[base + (size_t)((c + 1) * SCH + j) * (HK / 4)];
        }
#pragma unroll
        for (int j = 0; j < SCH; ++j) {
            const int t = c * SCH + j;
            float2 c01 = __half22float2(*(__half2*)&buf[cur][j].x);
            float2 c23 = __half22float2(*(__half2*)&buf[cur][j].y);
            d0 = be[0] * d0 + ob[0] * (c01.x + bi[0]);
            d1 = be[1] * d1 + ob[1] * (c01.y + bi[1]);
            d2 = be[2] * d2 + ob[2] * (c23.x + bi[2]);
            d3 = be[3] * d3 + ob[3] * (c23.y + bi[3]);
            m = al * m + oa * (d0 + d1 + d2 + d3) - sp;
            sp = (m > 1.0f) ? 1.0f : 0.0f;
            Sp[(size_t)t * HDIM] = __float2half_rn(sp);
        }
    }
}

__global__ void scan_readout_kernel(const float* __restrict__ br,
                                    const float* __restrict__ tau_mr,
                                    const void* __restrict__ warm,
                                    float* __restrict__ out, int boff) {
    const int o = threadIdx.x;
    const int b = boff + blockIdx.x;
    if (o >= ODIM) return;
    int w = *(const int*)warm;
    if (w < 0 || w > TSTEPS) w = (int)(*(const float*)warm);
    float al = 1.f / (1.f + expf(-tau_mr[o]));
    float oa = 1.f - al;
    float bo = br[o];

    const size_t base = (size_t)b * TSTEPS * NR + o;
    __half buf[2][SCH];
#pragma unroll
    for (int j = 0; j < SCH; ++j) buf[0][j] = g_C[base + (size_t)j * NR];

    float mr = 0.f, acc = 0.f;
    for (int c = 0; c < TSTEPS / SCH; ++c) {
        const int cur = c & 1;
        if (c + 1 < TSTEPS / SCH) {
#pragma unroll
            for (int j = 0; j < SCH; ++j)
                buf[cur ^ 1][j] = g_C[base + (size_t)((c + 1) * SCH + j) * NR];
        }
#pragma unroll
        for (int j = 0; j < SCH; ++j) {
            const int t = c * SCH + j;
            float v = __half2float(buf[cur][j]);
            mr = al * mr + oa * (v + bo);
            if (t >= w) acc += mr;
        }
    }
    out[b * ODIM + o] = acc / (float)(TSTEPS - w);
}

// ---------------- launch: symmetric 2-stream (R13 layout) ----------------
static cudaStream_t g_s1 = nullptr;
static cudaEvent_t g_ev0, g_evW, g_ev1;

extern "C" void kernel_launch(void* const* d_in, const int* in_sizes, int n_in,
                              void* d_out, int out_size) {
    const float* x      = (const float*)d_in[0];
    const float* W1     = (const float*)d_in[1];
    const float* b1     = (const float*)d_in[2];
    const float* tau_n1 = (const float*)d_in[3];
    const float* tau_m1 = (const float*)d_in[4];
    const float* W2     = (const float*)d_in[5];
    const float* b2     = (const float*)d_in[6];
    const float* tau_n2 = (const float*)d_in[7];
    const float* tau_m2 = (const float*)d_in[8];
    const float* Wr     = (const float*)d_in[9];
    const float* br     = (const float*)d_in[10];
    const float* tau_mr = (const float*)d_in[11];
    const void*  warm   = d_in[12];
    float* out = (float*)d_out;

    if (!g_s1) {
        cudaStreamCreateWithFlags(&g_s1, cudaStreamNonBlocking);
        cudaEventCreateWithFlags(&g_ev0, cudaEventDisableTiming);
        cudaEventCreateWithFlags(&g_evW, cudaEventDisableTiming);
        cudaEventCreateWithFlags(&g_ev1, cudaEventDisableTiming);
    }

    const int smem12 = NSTG * (128 + 128) * ROWB;  // 110592 per CTA
    const int smem3  = NSTG * (128 + 32) * ROWB;   // 69120
    cudaFuncSetAttribute(gemm1_k, cudaFuncAttributeMaxDynamicSharedMemorySize, smem12);
    cudaFuncSetAttribute(gemm2_k, cudaFuncAttributeMaxDynamicSharedMemorySize, smem12);
    cudaFuncSetAttribute(gemm3_k, cudaFuncAttributeMaxDynamicSharedMemorySize, smem3);

    const int xblk = (HROWS * (INPAD / 4)) / 256;   // 22000 per half

    // fork side stream
    cudaEventRecord(g_ev0, 0);
    cudaStreamWaitEvent(g_s1, g_ev0, 0);

    // default stream: weights, then half-0 chain
    prep_w_all<<<NW1B + NW2B + NWRB, 256>>>(W1, W2, Wr);
    cudaEventRecord(g_evW, 0);
    prep_x_kernel<<<xblk, 256>>>(x, 0);

    // side stream: half-1 chain
    prep_x_kernel<<<xblk, 256, 0, g_s1>>>(x, HROWS);
    cudaStreamWaitEvent(g_s1, g_evW, 0);
    gemm1_k<<<dim3(8, 250), 256, smem12, g_s1>>>(250);
    scan_layer_kernel<<<2 * HBATCH, 128, 0, g_s1>>>(b1, tau_n1, tau_m1, 0, HBATCH);
    gemm2_k<<<dim3(8, 250), 256, smem12, g_s1>>>(250);
    scan_layer_kernel<<<2 * HBATCH, 128, 0, g_s1>>>(b2, tau_n2, tau_m2, 1, HBATCH);
    gemm3_k<<<dim3(1, 250), 256, smem3, g_s1>>>(250);
    scan_readout_kernel<<<HBATCH, 32, 0, g_s1>>>(br, tau_mr, warm, out, HBATCH);
    cudaEventRecord(g_ev1, g_s1);

    // default stream: half-0 chain
    gemm1_k<<<dim3(8, 250), 256, smem12>>>(0);
    scan_layer_kernel<<<2 * HBATCH, 128>>>(b1, tau_n1, tau_m1, 0, 0);
    gemm2_k<<<dim3(8, 250), 256, smem12>>>(0);
    scan_layer_kernel<<<2 * HBATCH, 128>>>(b2, tau_n2, tau_m2, 1, 0);
    gemm3_k<<<dim3(1, 250), 256, smem3>>>(0);
    scan_readout_kernel<<<HBATCH, 32>>>(br, tau_mr, warm, out, 0);

    // join
    cudaStreamWaitEvent(0, g_ev1, 0);
}